// round 6
// baseline (speedup 1.0000x reference)
#include <cuda_runtime.h>
#include <math.h>

#define BB   32
#define SS   512
#define HH   512
#define EE   512
#define JPB  4
#define NTHR 512
#define TCHUNK 64

// ---------- global scratch ----------
__device__ float g_embg[(size_t)SS * 128 * 16 * BB];   // [t][bid(128)][ks(16)][b(32)]
__device__ unsigned long long g_ht2[2][256][BB];        // [buf][kpair][b]
__device__ unsigned g_flag[128];

union F2U { unsigned long long u; float2 f; };

__device__ __forceinline__ unsigned long long ffma2u(unsigned long long a,
                                                     unsigned long long b,
                                                     unsigned long long c) {
    unsigned long long d;
    asm("fma.rn.f32x2 %0, %1, %2, %3;" : "=l"(d) : "l"(a), "l"(b), "l"(c));
    return d;
}

__device__ __forceinline__ unsigned ld_acq(const unsigned* p) {
    unsigned v;
    asm volatile("ld.global.acquire.gpu.u32 %0, [%1];" : "=r"(v) : "l"(p) : "memory");
    return v;
}
__device__ __forceinline__ void st_rel(unsigned* p, unsigned v) {
    asm volatile("st.global.release.gpu.u32 [%0], %1;" :: "l"(p), "r"(v) : "memory");
}

__device__ __forceinline__ float sigmoidf_(float x) {
    return 1.0f / (1.0f + expf(-x));
}

// ======================================================================
// Phase 1: emb_gates. CTA owns 32 gate rows (8 h-indices), 64 tokens.
// Embeddings staged through smem with COALESCED loads.
// grid (64 rowpairs, 8 tchunks) x 512 threads.
// ======================================================================
#define P1_OFF_W    0          // 32*256 u64 = 65536
#define P1_OFF_PART 65536      // 16*32*32 f32 = 65536
#define P1_OFF_X    131072     // 256*33 u64 = 67584  (x_sh[kp*33 + b], padded)
#define P1_OFF_SEQ  198656     // 64*32 int = 8192
#define P1_SMEM     206848

__global__ __launch_bounds__(NTHR, 1)
void embg_kernel(const int* __restrict__ seq,
                 const float* __restrict__ emb_table,
                 const float* __restrict__ W_ih)
{
    extern __shared__ char smem[];
    unsigned long long* w2_sh  = (unsigned long long*)(smem + P1_OFF_W);
    float*              partf  = (float*)(smem + P1_OFF_PART);
    unsigned long long* x_sh   = (unsigned long long*)(smem + P1_OFF_X);
    int*                seq_sh = (int*)(smem + P1_OFF_SEQ);

    const int tid = threadIdx.x;
    const int ks  = tid >> 5;    // 0..15 k-split warp
    const int b   = tid & 31;    // batch lane
    const int rbp = blockIdx.x;  // rowpair block (h-indices 8*rbp..+7)
    const int t0  = blockIdx.y * TCHUNK;

    if (rbp == 0 && blockIdx.y == 0 && tid < 128) g_flag[tid] = 0u;  // reset for phase 2

    // stage 32 rows of W_e (K 0..511 as 256 u64 pairs per row)
    for (int idx = tid; idx < 32 * 256; idx += NTHR) {
        int r  = idx >> 8;
        int kp = idx & 255;
        int grow = (r >> 3) * HH + rbp * 8 + (r & 7);
        w2_sh[idx] = ((const unsigned long long*)(W_ih + (size_t)grow * (EE + HH)))[kp];
    }
    // seq_sh[tl*32 + r] = token of batch r at step t0+tl
    for (int i = tid; i < TCHUNK * BB; i += NTHR) {
        int tl = i >> 5, r = i & 31;
        seq_sh[i] = seq[r * SS + t0 + tl];
    }
    __syncthreads();

    // prologue: stage embeddings for tl=0 (coalesced: lanes span consecutive kp)
    #pragma unroll
    for (int i = 0; i < 16; i++) {
        int n  = i * NTHR + tid;
        int r  = n >> 8;           // batch row 0..31
        int kp = n & 255;          // u64 pair within row
        int token = seq_sh[r];
        x_sh[kp * 33 + r] = __ldg(
            (const unsigned long long*)(emb_table + (size_t)token * EE) + kp);
    }
    __syncthreads();

    for (int tl = 0; tl < TCHUNK; tl++) {
        // prefetch token rows for tl+1 into registers (coalesced)
        unsigned long long preg[16];
        if (tl + 1 < TCHUNK) {
            #pragma unroll
            for (int i = 0; i < 16; i++) {
                int n  = i * NTHR + tid;
                int r  = n >> 8;
                int kp = n & 255;
                int token = seq_sh[(tl + 1) * BB + r];
                preg[i] = __ldg(
                    (const unsigned long long*)(emb_table + (size_t)token * EE) + kp);
            }
        }

        // this thread's x chunk from smem (conflict-free: lanes span b)
        unsigned long long x[16];
        #pragma unroll
        for (int i = 0; i < 16; i++) x[i] = x_sh[(ks * 16 + i) * 33 + b];

        // two passes of 16 rows sharing x
        #pragma unroll
        for (int p = 0; p < 2; p++) {
            unsigned long long acc[16];
            #pragma unroll
            for (int r = 0; r < 16; r++) acc[r] = 0ull;
            #pragma unroll
            for (int i2 = 0; i2 < 8; i2++) {
                unsigned long long xa = x[2 * i2], xb = x[2 * i2 + 1];
                #pragma unroll
                for (int r = 0; r < 16; r++) {
                    ulonglong2 wv = *(const ulonglong2*)
                        (w2_sh + (p * 16 + r) * 256 + ks * 16 + 2 * i2);
                    acc[r] = ffma2u(xa, wv.x, ffma2u(xb, wv.y, acc[r]));
                }
            }
            #pragma unroll
            for (int r = 0; r < 16; r++) {
                F2U a; a.u = acc[r];
                partf[(ks * 32 + p * 16 + r) * BB + b] = a.f.x + a.f.y;
            }
        }
        __syncthreads();   // partf ready; x_sh reads done

        // overwrite x_sh with prefetched tl+1 data
        if (tl + 1 < TCHUNK) {
            #pragma unroll
            for (int i = 0; i < 16; i++) {
                int n  = i * NTHR + tid;
                x_sh[(n & 255) * 33 + (n >> 8)] = preg[i];
            }
        }

        // reduce: thread (ks,b) owns local rows ks and ks+16
        #pragma unroll
        for (int p = 0; p < 2; p++) {
            int rr = p * 16 + ks;
            float s = 0.f;
            #pragma unroll
            for (int kw = 0; kw < 16; kw++) s += partf[(kw * 32 + rr) * BB + b];
            int gate = rr >> 3, jj = rr & 7;
            int bid  = 2 * rbp + (jj >> 2);
            int ko   = gate * 4 + (jj & 3);
            g_embg[((size_t)(t0 + tl) * 128 + bid) * (16 * BB) + ko * BB + b] = s;
        }
        __syncthreads();
    }
}

// ======================================================================
// Phase 2: sequential LSTM, recurrent half (K=512). 128 CTAs x 512 thr
// Per-warp producer wait: warp ks polls only producers 8ks..8ks+7.
// ======================================================================
#define P2_OFF_W     0         // 16*256 u64 = 32768
#define P2_OFF_PART  32768     // 16*16*32 f32 = 32768
#define P2_OFF_CONST 65536     // 2048
#define P2_OFF_GSUM  67584     // 2048
#define P2_OFF_C0    69632     // 512
#define P2_SMEM      70400

__global__ __launch_bounds__(NTHR, 1)
void lstm_seq_kernel(const float* __restrict__ enc_h,
                     const float* __restrict__ enc_c,
                     const float* __restrict__ W_ih,
                     const float* __restrict__ W_hh,
                     const float* __restrict__ b_ih,
                     const float* __restrict__ b_hh,
                     float* __restrict__ out)
{
    extern __shared__ char smem[];
    unsigned long long* w2_sh = (unsigned long long*)(smem + P2_OFF_W);
    float*              partf = (float*)(smem + P2_OFF_PART);
    float*              cns_sh = (float*)(smem + P2_OFF_CONST);
    float*              gsum   = (float*)(smem + P2_OFF_GSUM);
    float*              c0_sh  = (float*)(smem + P2_OFF_C0);

    const int tid = threadIdx.x;
    const int bid = blockIdx.x;
    const int ks  = tid >> 5;
    const int b   = tid & 31;
    const int j0  = bid * JPB;

    for (int idx = tid; idx < 16 * 256; idx += NTHR) {
        int r  = idx >> 8;
        int kp = idx & 255;
        int grow = (r >> 2) * HH + j0 + (r & 3);
        w2_sh[idx] = ((const unsigned long long*)(W_ih + (size_t)grow * (EE + HH)))[256 + kp];
    }
    if (tid < 128) c0_sh[ks * BB + b] = enc_c[b * HH + j0 + ks];
    __syncthreads();

    // const = h0 @ W_hh^T + b_ih + b_hh
    {
        float h0c[32];
        #pragma unroll
        for (int i = 0; i < 32; i++) h0c[i] = enc_h[b * HH + ks * 32 + i];
        #pragma unroll
        for (int r = 0; r < 16; r++) {
            const float* wr = W_hh + (size_t)((r >> 2) * HH + j0 + (r & 3)) * HH + ks * 32;
            float acc = 0.f;
            #pragma unroll
            for (int i = 0; i < 32; i++) acc = fmaf(h0c[i], wr[i], acc);
            partf[(ks * 16 + r) * BB + b] = acc;
        }
        __syncthreads();
        {
            float s = 0.f;
            #pragma unroll
            for (int k2 = 0; k2 < 16; k2++) s += partf[(k2 * 16 + ks) * BB + b];
            int grow = (ks >> 2) * HH + j0 + (ks & 3);
            cns_sh[ks * BB + b] = s + b_ih[grow] + b_hh[grow];
        }
        __syncthreads();
    }

    const int pidx = ks * 8 + (b & 7);   // producer flag this lane polls

    for (int t = 0; t < SS; t++) {
        // emb-gate contribution: independent of h, issue before the wait
        float embv = __ldcg(&g_embg[((size_t)t * 128 + bid) * (16 * BB) + ks * BB + b]);

        unsigned long long x[16];
        if (t > 0) {
            // warp-local wait: only the 8 producers covering this warp's K-chunk
            while (ld_acq(&g_flag[pidx]) < (unsigned)t) { }
            __syncwarp();
            const unsigned long long* hb = &g_ht2[(t - 1) & 1][ks * 16][0];
            #pragma unroll
            for (int i = 0; i < 16; i++) x[i] = __ldcg(&hb[i * BB + b]);
        } else {
            #pragma unroll
            for (int i = 0; i < 16; i++) x[i] = 0ull;
        }

        unsigned long long acc[16];
        #pragma unroll
        for (int r = 0; r < 16; r++) acc[r] = 0ull;
        #pragma unroll
        for (int i2 = 0; i2 < 8; i2++) {
            unsigned long long xa = x[2 * i2], xb = x[2 * i2 + 1];
            #pragma unroll
            for (int r = 0; r < 16; r++) {
                ulonglong2 wv = *(const ulonglong2*)(w2_sh + r * 256 + ks * 16 + 2 * i2);
                acc[r] = ffma2u(xa, wv.x, ffma2u(xb, wv.y, acc[r]));
            }
        }
        #pragma unroll
        for (int r = 0; r < 16; r++) {
            F2U a; a.u = acc[r];
            partf[(ks * 16 + r) * BB + b] = a.f.x + a.f.y;
        }
        __syncthreads();   // sync#1: partf ready

        {
            float s = 0.f;
            #pragma unroll
            for (int k2 = 0; k2 < 16; k2++) s += partf[(k2 * 16 + ks) * BB + b];
            gsum[ks * BB + b] = s + cns_sh[ks * BB + b] + embv;
        }
        __syncthreads();   // sync#2: gsum ready; warps 4-15 proceed to next poll

        if (tid < 128) {
            int jj = ks;
            float iv = gsum[(0 * 4 + jj) * BB + b];
            float fv = gsum[(1 * 4 + jj) * BB + b];
            float gv = gsum[(2 * 4 + jj) * BB + b];
            float ov = gsum[(3 * 4 + jj) * BB + b];
            float ig = sigmoidf_(iv);
            float fg = sigmoidf_(fv);
            float gg = tanhf(gv);
            float og = sigmoidf_(ov);
            float cc = fg * c0_sh[jj * BB + b] + ig * gg;
            float hh = og * tanhf(cc);
            float* hp = (float*)&g_ht2[t & 1][2 * bid + (jj >> 1)][b];
            hp[jj & 1] = hh;

            asm volatile("bar.sync 1, 128;" ::: "memory");
            if (tid == 0) {
                __threadfence();
                st_rel(&g_flag[bid], (unsigned)(t + 1));
            }
            out[(size_t)b * (SS * HH) + (size_t)t * HH + j0 + jj] = hh;
        }
        // no end-of-step CTA barrier: partf/gsum reuse is gated by sync#1/#2
        // and the publish-gated poll (no CTA can run 2 steps ahead).
    }
}

extern "C" void kernel_launch(void* const* d_in, const int* in_sizes, int n_in,
                              void* d_out, int out_size) {
    const int*   seq   = (const int*)d_in[0];
    // d_in[1] = enc_out : unused
    const float* enc_h = (const float*)d_in[2];
    const float* enc_c = (const float*)d_in[3];
    const float* emb   = (const float*)d_in[4];
    const float* W_ih  = (const float*)d_in[5];
    const float* W_hh  = (const float*)d_in[6];
    const float* b_ih  = (const float*)d_in[7];
    const float* b_hh  = (const float*)d_in[8];
    float* out = (float*)d_out;

    static bool attr_set = false;
    if (!attr_set) {
        cudaFuncSetAttribute(embg_kernel,
                             cudaFuncAttributeMaxDynamicSharedMemorySize, P1_SMEM);
        cudaFuncSetAttribute(lstm_seq_kernel,
                             cudaFuncAttributeMaxDynamicSharedMemorySize, P2_SMEM);
        attr_set = true;
    }

    dim3 g1(64, SS / TCHUNK);
    embg_kernel<<<g1, NTHR, P1_SMEM>>>(seq, emb, W_ih);
    lstm_seq_kernel<<<128, NTHR, P2_SMEM>>>(enc_h, enc_c, W_ih, W_hh,
                                            b_ih, b_hh, out);
}

// round 8
// speedup vs baseline: 1.3032x; 1.3032x over previous
#include <cuda_runtime.h>
#include <math.h>

#define BB   32
#define SS   512
#define HH   512
#define EE   512
#define JPB  4
#define NTHR 512
#define TCHUNK 64

// ---------- global scratch ----------
__device__ float g_embg[(size_t)SS * 128 * 16 * BB];   // [t][bid(128)][ks(16)][b(32)]
// tagged h pairs: [buf][jpair(256)][b]; each u64 = {h[2j],h[2j+1]} with 3 LSB tag per float
__device__ unsigned long long g_htag[2][256][BB];

union F2U { unsigned long long u; float2 f; };

__device__ __forceinline__ unsigned long long ffma2u(unsigned long long a,
                                                     unsigned long long b,
                                                     unsigned long long c) {
    unsigned long long d;
    asm("fma.rn.f32x2 %0, %1, %2, %3;" : "=l"(d) : "l"(a), "l"(b), "l"(c));
    return d;
}

__device__ __forceinline__ unsigned long long ld_rlx(const unsigned long long* p) {
    unsigned long long v;
    asm volatile("ld.relaxed.gpu.b64 %0, [%1];" : "=l"(v) : "l"(p) : "memory");
    return v;
}
__device__ __forceinline__ void st_rlx(unsigned long long* p, unsigned long long v) {
    asm volatile("st.relaxed.gpu.b64 [%0], %1;" :: "l"(p), "l"(v) : "memory");
}

__device__ __forceinline__ float sigmoidf_(float x) {
    return 1.0f / (1.0f + expf(-x));
}

// ======================================================================
// Phase 1: emb_gates (unchanged R6 structure) + clears g_htag tags.
// grid (64 rowpairs, 8 tchunks) x 512 threads.
// ======================================================================
#define P1_OFF_W    0          // 32*256 u64 = 65536
#define P1_OFF_PART 65536      // 16*32*32 f32 = 65536
#define P1_OFF_X    131072     // 256*33 u64 = 67584
#define P1_OFF_SEQ  198656     // 64*32 int = 8192
#define P1_SMEM     206848

__global__ __launch_bounds__(NTHR, 1)
void embg_kernel(const int* __restrict__ seq,
                 const float* __restrict__ emb_table,
                 const float* __restrict__ W_ih)
{
    extern __shared__ char smem[];
    unsigned long long* w2_sh  = (unsigned long long*)(smem + P1_OFF_W);
    float*              partf  = (float*)(smem + P1_OFF_PART);
    unsigned long long* x_sh   = (unsigned long long*)(smem + P1_OFF_X);
    int*                seq_sh = (int*)(smem + P1_OFF_SEQ);

    const int tid = threadIdx.x;
    const int ks  = tid >> 5;
    const int b   = tid & 31;
    const int rbp = blockIdx.x;
    const int t0  = blockIdx.y * TCHUNK;

    // clear tagged h buffers (valid bit -> 0) so phase 2 never reads stale runs
    if (blockIdx.y == 0) {
        int n = rbp * NTHR + tid;           // 64*512 = 32768 >= 16384 words
        if (n < 2 * 256 * BB) ((unsigned long long*)g_htag)[n] = 0ull;
    }

    for (int idx = tid; idx < 32 * 256; idx += NTHR) {
        int r  = idx >> 8;
        int kp = idx & 255;
        int grow = (r >> 3) * HH + rbp * 8 + (r & 7);
        w2_sh[idx] = ((const unsigned long long*)(W_ih + (size_t)grow * (EE + HH)))[kp];
    }
    for (int i = tid; i < TCHUNK * BB; i += NTHR) {
        int tl = i >> 5, r = i & 31;
        seq_sh[i] = seq[r * SS + t0 + tl];
    }
    __syncthreads();

    // prologue: coalesced embedding stage for tl=0
    #pragma unroll
    for (int i = 0; i < 16; i++) {
        int n  = i * NTHR + tid;
        int r  = n >> 8;
        int kp = n & 255;
        int token = seq_sh[r];
        x_sh[kp * 33 + r] = __ldg(
            (const unsigned long long*)(emb_table + (size_t)token * EE) + kp);
    }
    __syncthreads();

    for (int tl = 0; tl < TCHUNK; tl++) {
        unsigned long long preg[16];
        if (tl + 1 < TCHUNK) {
            #pragma unroll
            for (int i = 0; i < 16; i++) {
                int n  = i * NTHR + tid;
                int r  = n >> 8;
                int kp = n & 255;
                int token = seq_sh[(tl + 1) * BB + r];
                preg[i] = __ldg(
                    (const unsigned long long*)(emb_table + (size_t)token * EE) + kp);
            }
        }

        unsigned long long x[16];
        #pragma unroll
        for (int i = 0; i < 16; i++) x[i] = x_sh[(ks * 16 + i) * 33 + b];

        #pragma unroll
        for (int p = 0; p < 2; p++) {
            unsigned long long acc[16];
            #pragma unroll
            for (int r = 0; r < 16; r++) acc[r] = 0ull;
            #pragma unroll
            for (int i2 = 0; i2 < 8; i2++) {
                unsigned long long xa = x[2 * i2], xb = x[2 * i2 + 1];
                #pragma unroll
                for (int r = 0; r < 16; r++) {
                    ulonglong2 wv = *(const ulonglong2*)
                        (w2_sh + (p * 16 + r) * 256 + ks * 16 + 2 * i2);
                    acc[r] = ffma2u(xa, wv.x, ffma2u(xb, wv.y, acc[r]));
                }
            }
            #pragma unroll
            for (int r = 0; r < 16; r++) {
                F2U a; a.u = acc[r];
                partf[(ks * 32 + p * 16 + r) * BB + b] = a.f.x + a.f.y;
            }
        }
        __syncthreads();

        if (tl + 1 < TCHUNK) {
            #pragma unroll
            for (int i = 0; i < 16; i++) {
                int n  = i * NTHR + tid;
                x_sh[(n & 255) * 33 + (n >> 8)] = preg[i];
            }
        }

        #pragma unroll
        for (int p = 0; p < 2; p++) {
            int rr = p * 16 + ks;
            float s = 0.f;
            #pragma unroll
            for (int kw = 0; kw < 16; kw++) s += partf[(kw * 32 + rr) * BB + b];
            int gate = rr >> 3, jj = rr & 7;
            int bid  = 2 * rbp + (jj >> 2);
            int ko   = gate * 4 + (jj & 3);
            g_embg[((size_t)(t0 + tl) * 128 + bid) * (16 * BB) + ko * BB + b] = s;
        }
        __syncthreads();
    }
}

// ======================================================================
// Phase 2: sequential LSTM with tagged-word handoff. 128 CTAs x 512 thr
// ======================================================================
#define P2_OFF_W     0         // 16*256 u64 = 32768
#define P2_OFF_PART  32768     // 16*16*32 f32 = 32768
#define P2_OFF_CONST 65536     // 2048
#define P2_OFF_GSUM  67584     // 2048
#define P2_OFF_C0    69632     // 512
#define P2_SMEM      70400

__global__ __launch_bounds__(NTHR, 1)
void lstm_seq_kernel(const float* __restrict__ enc_h,
                     const float* __restrict__ enc_c,
                     const float* __restrict__ W_ih,
                     const float* __restrict__ W_hh,
                     const float* __restrict__ b_ih,
                     const float* __restrict__ b_hh,
                     float* __restrict__ out)
{
    extern __shared__ char smem[];
    unsigned long long* w2_sh = (unsigned long long*)(smem + P2_OFF_W);
    float*              partf = (float*)(smem + P2_OFF_PART);
    float*              cns_sh = (float*)(smem + P2_OFF_CONST);
    float*              gsum   = (float*)(smem + P2_OFF_GSUM);
    float*              c0_sh  = (float*)(smem + P2_OFF_C0);

    const int tid = threadIdx.x;
    const int bid = blockIdx.x;
    const int ks  = tid >> 5;
    const int b   = tid & 31;
    const int j0  = bid * JPB;

    for (int idx = tid; idx < 16 * 256; idx += NTHR) {
        int r  = idx >> 8;
        int kp = idx & 255;
        int grow = (r >> 2) * HH + j0 + (r & 3);
        w2_sh[idx] = ((const unsigned long long*)(W_ih + (size_t)grow * (EE + HH)))[256 + kp];
    }
    if (tid < 128) c0_sh[ks * BB + b] = enc_c[b * HH + j0 + ks];
    __syncthreads();

    // const = h0 @ W_hh^T + b_ih + b_hh
    {
        float h0c[32];
        #pragma unroll
        for (int i = 0; i < 32; i++) h0c[i] = enc_h[b * HH + ks * 32 + i];
        #pragma unroll
        for (int r = 0; r < 16; r++) {
            const float* wr = W_hh + (size_t)((r >> 2) * HH + j0 + (r & 3)) * HH + ks * 32;
            float acc = 0.f;
            #pragma unroll
            for (int i = 0; i < 32; i++) acc = fmaf(h0c[i], wr[i], acc);
            partf[(ks * 16 + r) * BB + b] = acc;
        }
        __syncthreads();
        {
            float s = 0.f;
            #pragma unroll
            for (int k2 = 0; k2 < 16; k2++) s += partf[(k2 * 16 + ks) * BB + b];
            int grow = (ks >> 2) * HH + j0 + (ks & 3);
            cns_sh[ks * BB + b] = s + b_ih[grow] + b_hh[grow];
        }
        __syncthreads();
    }

    for (int t = 0; t < SS; t++) {
        // emb-gate contribution: independent of h, issue first
        float embv = __ldcg(&g_embg[((size_t)t * 128 + bid) * (16 * BB) + ks * BB + b]);

        unsigned long long x[16];
        if (t > 0) {
            const unsigned long long* hb = &g_htag[(t - 1) & 1][ks * 16][0];
            const unsigned want = 4u | ((unsigned)t & 3u);
            // batch-issue all 16 loads, then validate+retry each
            #pragma unroll
            for (int i = 0; i < 16; i++) x[i] = ld_rlx(&hb[i * BB + b]);
            #pragma unroll
            for (int i = 0; i < 16; i++) {
                while (((unsigned)x[i] & 7u) != want)
                    x[i] = ld_rlx(&hb[i * BB + b]);
            }
        } else {
            #pragma unroll
            for (int i = 0; i < 16; i++) x[i] = 0ull;
        }

        unsigned long long acc[16];
        #pragma unroll
        for (int r = 0; r < 16; r++) acc[r] = 0ull;
        #pragma unroll
        for (int i2 = 0; i2 < 8; i2++) {
            unsigned long long xa = x[2 * i2], xb = x[2 * i2 + 1];
            #pragma unroll
            for (int r = 0; r < 16; r++) {
                ulonglong2 wv = *(const ulonglong2*)(w2_sh + r * 256 + ks * 16 + 2 * i2);
                acc[r] = ffma2u(xa, wv.x, ffma2u(xb, wv.y, acc[r]));
            }
        }
        #pragma unroll
        for (int r = 0; r < 16; r++) {
            F2U a; a.u = acc[r];
            partf[(ks * 16 + r) * BB + b] = a.f.x + a.f.y;
        }
        __syncthreads();   // sync#1: partf ready

        {
            float s = 0.f;
            #pragma unroll
            for (int k2 = 0; k2 < 16; k2++) s += partf[(k2 * 16 + ks) * BB + b];
            gsum[ks * BB + b] = s + cns_sh[ks * BB + b] + embv;
        }
        __syncthreads();   // sync#2: gsum ready

        // nonlin: 64 threads, thread (p,b) computes the pair h[2p], h[2p+1],
        // publishes ONE tagged 64-bit word (no fence/flag/barrier needed).
        if (tid < 64) {
            int p  = tid >> 5;       // 0..1
            int bb = tid & 31;
            float h2[2];
            #pragma unroll
            for (int q = 0; q < 2; q++) {
                int jj = 2 * p + q;
                float iv = gsum[(0 * 4 + jj) * BB + bb];
                float fv = gsum[(1 * 4 + jj) * BB + bb];
                float gv = gsum[(2 * 4 + jj) * BB + bb];
                float ov = gsum[(3 * 4 + jj) * BB + bb];
                float ig = sigmoidf_(iv);
                float fg = sigmoidf_(fv);
                float gg = tanhf(gv);
                float og = sigmoidf_(ov);
                float cc = fg * c0_sh[jj * BB + bb] + ig * gg;
                h2[q] = og * tanhf(cc);
            }
            unsigned field = 4u | ((unsigned)(t + 1) & 3u);
            unsigned lo = (__float_as_uint(h2[0]) & ~7u) | field;
            unsigned hi = (__float_as_uint(h2[1]) & ~7u) | field;
            st_rlx(&g_htag[t & 1][2 * bid + p][bb],
                   (unsigned long long)lo | ((unsigned long long)hi << 32));
            // full-precision output store (off critical path)
            float2 o = make_float2(h2[0], h2[1]);
            *(float2*)(out + (size_t)bb * (SS * HH) + (size_t)t * HH + j0 + 2 * p) = o;
        }
        // no end-of-step barrier: partf/gsum reuse protected by sync#1/#2,
        // cross-CTA skew bounded by tag dependencies (<=1 step).
    }
}

extern "C" void kernel_launch(void* const* d_in, const int* in_sizes, int n_in,
                              void* d_out, int out_size) {
    const int*   seq   = (const int*)d_in[0];
    // d_in[1] = enc_out : unused
    const float* enc_h = (const float*)d_in[2];
    const float* enc_c = (const float*)d_in[3];
    const float* emb   = (const float*)d_in[4];
    const float* W_ih  = (const float*)d_in[5];
    const float* W_hh  = (const float*)d_in[6];
    const float* b_ih  = (const float*)d_in[7];
    const float* b_hh  = (const float*)d_in[8];
    float* out = (float*)d_out;

    static bool attr_set = false;
    if (!attr_set) {
        cudaFuncSetAttribute(embg_kernel,
                             cudaFuncAttributeMaxDynamicSharedMemorySize, P1_SMEM);
        cudaFuncSetAttribute(lstm_seq_kernel,
                             cudaFuncAttributeMaxDynamicSharedMemorySize, P2_SMEM);
        attr_set = true;
    }

    dim3 g1(64, SS / TCHUNK);
    embg_kernel<<<g1, NTHR, P1_SMEM>>>(seq, emb, W_ih);
    lstm_seq_kernel<<<128, NTHR, P2_SMEM>>>(enc_h, enc_c, W_ih, W_hh,
                                            b_ih, b_hh, out);
}